// round 1
// baseline (speedup 1.0000x reference)
#include <cuda_runtime.h>
#include <cuda_bf16.h>

#define NN 50000
#define EE 800000
#define CC 256
#define NOUTD 64

#define BM 128
#define BN 64
#define BK 32
#define PK 40   // padded bf16 row stride (conflict-free for mma fragment loads)

// ---------------- scratch (no allocations allowed) ----------------
__device__ float g_s0[(size_t)NN * CC];
__device__ float g_s1[(size_t)NN * CC];
__device__ int g_deg[NN];
__device__ int g_off[NN + 1];
__device__ int g_pos[NN];
__device__ int g_csr[EE];

// ---------------- CSR build ----------------
__global__ void k_zero(int* p, int n) {
    int i = blockIdx.x * blockDim.x + threadIdx.x;
    if (i < n) p[i] = 0;
}

__global__ void k_count(const int* __restrict__ dst, int* deg) {
    int e = blockIdx.x * blockDim.x + threadIdx.x;
    if (e < EE) atomicAdd(&deg[dst[e]], 1);
}

__global__ void k_scan(const int* __restrict__ deg, int* off, int* pos) {
    __shared__ int wtot[32];
    int tid = threadIdx.x, lane = tid & 31, w = tid >> 5;
    int running = 0;
    for (int base = 0; base < NN; base += 1024) {
        int i = base + tid;
        int v = (i < NN) ? deg[i] : 0;
        int incl = v;
#pragma unroll
        for (int s = 1; s < 32; s <<= 1) {
            int t = __shfl_up_sync(0xffffffffu, incl, s);
            if (lane >= s) incl += t;
        }
        if (lane == 31) wtot[w] = incl;
        __syncthreads();
        if (tid < 32) {
            int t = wtot[tid];
#pragma unroll
            for (int s = 1; s < 32; s <<= 1) {
                int u = __shfl_up_sync(0xffffffffu, t, s);
                if (tid >= s) t += u;
            }
            wtot[tid] = t;
        }
        __syncthreads();
        int woff = (w == 0) ? 0 : wtot[w - 1];
        int excl = running + woff + incl - v;
        if (i < NN) { off[i] = excl; pos[i] = excl; }
        int tot = wtot[31];
        __syncthreads();
        running += tot;
    }
    if (tid == 0) off[NN] = running;
}

__global__ void k_scatter(const int* __restrict__ src, const int* __restrict__ dst,
                          int* pos, int* csr) {
    int e = blockIdx.x * blockDim.x + threadIdx.x;
    if (e < EE) {
        int p = atomicAdd(&pos[dst[e]], 1);
        csr[p] = src[e];
    }
}

// ---------------- aggregation: out[v] = x[v] + sum_{u in N(v)} x[u] ----------------
__global__ void __launch_bounds__(256) k_agg(const float* __restrict__ x,
                                             const int* __restrict__ off,
                                             const int* __restrict__ csr,
                                             float* __restrict__ out) {
    int wid = (blockIdx.x * blockDim.x + threadIdx.x) >> 5;
    int lane = threadIdx.x & 31;
    if (wid >= NN) return;
    const float4* x4 = (const float4*)x;
    size_t rb = (size_t)wid * 64;  // 256 floats = 64 float4 per row
    float4 a0 = x4[rb + lane];
    float4 a1 = x4[rb + 32 + lane];
    int s = off[wid], e = off[wid + 1];
    for (int i = s; i < e; i++) {
        size_t ub = (size_t)csr[i] * 64;
        float4 v0 = x4[ub + lane];
        float4 v1 = x4[ub + 32 + lane];
        a0.x += v0.x; a0.y += v0.y; a0.z += v0.z; a0.w += v0.w;
        a1.x += v1.x; a1.y += v1.y; a1.z += v1.z; a1.w += v1.w;
    }
    float4* o4 = (float4*)out;
    o4[rb + lane] = a0;
    o4[rb + 32 + lane] = a1;
}

// ---------------- GEMM (split-bf16 3-product "fp32-accurate" tensor core) ----------------
__device__ __forceinline__ void split2(float v, __nv_bfloat16& h, __nv_bfloat16& l) {
    h = __float2bfloat16(v);
    l = __float2bfloat16(v - __bfloat162float(h));
}

#define MMA(C_, A_, B_)                                                          \
    asm volatile(                                                                \
        "mma.sync.aligned.m16n8k16.row.col.f32.bf16.bf16.f32 "                   \
        "{%0,%1,%2,%3}, {%4,%5,%6,%7}, {%8,%9}, {%0,%1,%2,%3};\n"                \
        : "+f"(C_[0]), "+f"(C_[1]), "+f"(C_[2]), "+f"(C_[3])                     \
        : "r"(A_[0]), "r"(A_[1]), "r"(A_[2]), "r"(A_[3]), "r"(B_[0]), "r"(B_[1]))

__global__ void __launch_bounds__(256) k_gemm(const float* __restrict__ A,
                                              const float* __restrict__ W,
                                              const float* __restrict__ bias,
                                              float* __restrict__ out,
                                              int M, int K, int Nout, int relu) {
    __shared__ __align__(16) __nv_bfloat16 sAh[BM * PK];
    __shared__ __align__(16) __nv_bfloat16 sAl[BM * PK];
    __shared__ __align__(16) __nv_bfloat16 sBh[BN * PK];
    __shared__ __align__(16) __nv_bfloat16 sBl[BN * PK];

    int tid = threadIdx.x, lane = tid & 31, warp = tid >> 5;
    int g = lane >> 2, tig = lane & 3;
    int wm = warp >> 1, wn = warp & 1;     // 4x2 warp grid, each warp 32x32
    int m0 = blockIdx.x * BM, n0 = blockIdx.y * BN;

    float c[2][4][4];
#pragma unroll
    for (int m = 0; m < 2; m++)
#pragma unroll
        for (int n = 0; n < 4; n++)
#pragma unroll
            for (int i = 0; i < 4; i++) c[m][n][i] = 0.f;

    for (int kt = 0; kt < K; kt += BK) {
        // stage A tile 128x32 fp32 -> bf16 hi/lo
#pragma unroll
        for (int i = 0; i < 4; i++) {
            int f = tid + i * 256;
            int r = f >> 3, c4 = (f & 7) << 2;
            int gr = m0 + r;
            float4 v = make_float4(0.f, 0.f, 0.f, 0.f);
            if (gr < M) v = *(const float4*)(A + (size_t)gr * K + kt + c4);
            __nv_bfloat16 h0, l0, h1, l1, h2, l2, h3, l3;
            split2(v.x, h0, l0); split2(v.y, h1, l1);
            split2(v.z, h2, l2); split2(v.w, h3, l3);
            __nv_bfloat162* ph = (__nv_bfloat162*)&sAh[r * PK + c4];
            ph[0] = __halves2bfloat162(h0, h1);
            ph[1] = __halves2bfloat162(h2, h3);
            __nv_bfloat162* pl = (__nv_bfloat162*)&sAl[r * PK + c4];
            pl[0] = __halves2bfloat162(l0, l1);
            pl[1] = __halves2bfloat162(l2, l3);
        }
        // stage B tile 32x64 fp32 -> transposed bf16 hi/lo ( sB[n][k] )
#pragma unroll
        for (int i = 0; i < 2; i++) {
            int f = tid + i * 256;
            int kk = f >> 4, nn = (f & 15) << 2;
            float4 v = *(const float4*)(W + (size_t)(kt + kk) * Nout + n0 + nn);
            __nv_bfloat16 h, l;
            split2(v.x, h, l); sBh[(nn + 0) * PK + kk] = h; sBl[(nn + 0) * PK + kk] = l;
            split2(v.y, h, l); sBh[(nn + 1) * PK + kk] = h; sBl[(nn + 1) * PK + kk] = l;
            split2(v.z, h, l); sBh[(nn + 2) * PK + kk] = h; sBl[(nn + 2) * PK + kk] = l;
            split2(v.w, h, l); sBh[(nn + 3) * PK + kk] = h; sBl[(nn + 3) * PK + kk] = l;
        }
        __syncthreads();

#pragma unroll
        for (int ks = 0; ks < 2; ks++) {
            int kb = ks * 16;
            unsigned aH[2][4], aL[2][4], bH[4][2], bL[4][2];
#pragma unroll
            for (int m = 0; m < 2; m++) {
                int row = wm * 32 + m * 16 + g;
                const __nv_bfloat16* p = &sAh[row * PK + kb + 2 * tig];
                const __nv_bfloat16* q = &sAl[row * PK + kb + 2 * tig];
                aH[m][0] = *(const unsigned*)p;
                aH[m][1] = *(const unsigned*)(p + 8 * PK);
                aH[m][2] = *(const unsigned*)(p + 8);
                aH[m][3] = *(const unsigned*)(p + 8 * PK + 8);
                aL[m][0] = *(const unsigned*)q;
                aL[m][1] = *(const unsigned*)(q + 8 * PK);
                aL[m][2] = *(const unsigned*)(q + 8);
                aL[m][3] = *(const unsigned*)(q + 8 * PK + 8);
            }
#pragma unroll
            for (int n = 0; n < 4; n++) {
                int col = wn * 32 + n * 8 + g;
                const __nv_bfloat16* p = &sBh[col * PK + kb + 2 * tig];
                const __nv_bfloat16* q = &sBl[col * PK + kb + 2 * tig];
                bH[n][0] = *(const unsigned*)p;
                bH[n][1] = *(const unsigned*)(p + 8);
                bL[n][0] = *(const unsigned*)q;
                bL[n][1] = *(const unsigned*)(q + 8);
            }
#pragma unroll
            for (int m = 0; m < 2; m++)
#pragma unroll
                for (int n = 0; n < 4; n++) {
                    MMA(c[m][n], aH[m], bH[n]);
                    MMA(c[m][n], aH[m], bL[n]);
                    MMA(c[m][n], aL[m], bH[n]);
                }
        }
        __syncthreads();
    }

    // epilogue: bias + optional relu
#pragma unroll
    for (int m = 0; m < 2; m++) {
        int row = m0 + wm * 32 + m * 16 + g;
#pragma unroll
        for (int n = 0; n < 4; n++) {
            int col = n0 + wn * 32 + n * 8 + 2 * tig;
            float b0 = bias[col], b1 = bias[col + 1];
            float v0 = c[m][n][0] + b0, v1 = c[m][n][1] + b1;
            float v2 = c[m][n][2] + b0, v3 = c[m][n][3] + b1;
            if (relu) {
                v0 = fmaxf(v0, 0.f); v1 = fmaxf(v1, 0.f);
                v2 = fmaxf(v2, 0.f); v3 = fmaxf(v3, 0.f);
            }
            if (row < M) {
                out[(size_t)row * Nout + col] = v0;
                out[(size_t)row * Nout + col + 1] = v1;
            }
            if (row + 8 < M) {
                out[(size_t)(row + 8) * Nout + col] = v2;
                out[(size_t)(row + 8) * Nout + col + 1] = v3;
            }
        }
    }
}

// ---------------- launch ----------------
extern "C" void kernel_launch(void* const* d_in, const int* in_sizes, int n_in,
                              void* d_out, int out_size) {
    const float* x   = (const float*)d_in[0];
    const int*   src = (const int*)d_in[1];
    const int*   dst = (const int*)d_in[2];
    const float* W1s = (const float*)d_in[3];
    const float* b1s = (const float*)d_in[4];
    const float* W2s = (const float*)d_in[5];
    const float* b2s = (const float*)d_in[6];
    const float* W3s = (const float*)d_in[7];
    const float* b3s = (const float*)d_in[8];
    const float* cW1 = (const float*)d_in[9];
    const float* cb1 = (const float*)d_in[10];
    const float* cW2 = (const float*)d_in[11];
    const float* cb2 = (const float*)d_in[12];
    const float* cW3 = (const float*)d_in[13];
    const float* cb3 = (const float*)d_in[14];
    float* out = (float*)d_out;

    float *s0, *s1;
    int *deg, *off, *pos, *csr;
    cudaGetSymbolAddress((void**)&s0, g_s0);
    cudaGetSymbolAddress((void**)&s1, g_s1);
    cudaGetSymbolAddress((void**)&deg, g_deg);
    cudaGetSymbolAddress((void**)&off, g_off);
    cudaGetSymbolAddress((void**)&pos, g_pos);
    cudaGetSymbolAddress((void**)&csr, g_csr);

    // CSR build (per call; graph-capturable, int atomics only)
    k_zero<<<(NN + 255) / 256, 256>>>(deg, NN);
    k_count<<<(EE + 255) / 256, 256>>>(dst, deg);
    k_scan<<<1, 1024>>>(deg, off, pos);
    k_scatter<<<(EE + 255) / 256, 256>>>(src, dst, pos, csr);

    dim3 gFull((NN + BM - 1) / BM, CC / BN);   // (391, 4)
    dim3 gN64((NN + BM - 1) / BM, 1);          // Nout = 64
    int aggBlocks = (NN + 7) / 8;              // 8 warps/block, warp per node

    const float* X = x;
    for (int l = 0; l < 3; l++) {
        k_agg<<<aggBlocks, 256>>>(X, off, csr, s0);
        k_gemm<<<gFull, 256>>>(s0, W1s + (size_t)l * CC * CC, b1s + (size_t)l * CC, s1, NN, CC, CC, 1);
        k_gemm<<<gFull, 256>>>(s1, W2s + (size_t)l * CC * CC, b2s + (size_t)l * CC, s0, NN, CC, CC, 1);
        k_gemm<<<gFull, 256>>>(s0, W3s + (size_t)l * CC * CC, b3s + (size_t)l * CC, s1, NN, CC, CC, 0);
        X = s1;
    }
    k_agg<<<aggBlocks, 256>>>(X, off, csr, s0);
    k_gemm<<<gFull, 256>>>(s0, cW1, cb1, s1, NN, CC, CC, 1);
    k_gemm<<<gN64, 256>>>(s1, cW2, cb2, s0, NN, CC, NOUTD, 1);
    k_gemm<<<gFull, 256>>>(s0, cW3, cb3, out, NN, NOUTD, CC, 0);
}

// round 3
// speedup vs baseline: 1.4084x; 1.4084x over previous
#include <cuda_runtime.h>
#include <cuda_bf16.h>
#include <cstdint>

#define NN 50000
#define EE 800000
#define CC 256

#define PK 40            // padded bf16 row stride in smem (conflict-free, verified R1)
#define MAT_B 10240u     // one 128xPK bf16 matrix = 128*40*2 bytes
#define STAGE_B 40960u   // Ah+Al+Bh+Bl per stage

// ---------------- scratch (device globals; no allocations) ----------------
__device__ __align__(16) float g_s0[(size_t)NN * CC];
__device__ __align__(16) __nv_bfloat16 g_pAh[(size_t)NN * CC];
__device__ __align__(16) __nv_bfloat16 g_pAl[(size_t)NN * CC];
__device__ __align__(16) __nv_bfloat16 g_pBh[(size_t)NN * CC];
__device__ __align__(16) __nv_bfloat16 g_pBl[(size_t)NN * CC];
#define WOFF_INNER(l, j) ((size_t)((l)*3 + (j)) * 65536)
#define WOFF_CW1 589824
#define WOFF_CW2 655360
#define WOFF_CW3 671744
__device__ __align__(16) __nv_bfloat16 g_wh[688128];
__device__ __align__(16) __nv_bfloat16 g_wl[688128];
__device__ int g_deg[NN];
__device__ int g_off[NN + 1];
__device__ int g_pos[NN];
__device__ int g_csr[EE];

// ---------------- PTX helpers ----------------
__device__ __forceinline__ uint32_t s2u(const void* p) {
    uint32_t a;
    asm("{ .reg .u64 t; cvta.to.shared.u64 t, %1; cvt.u32.u64 %0, t; }" : "=r"(a) : "l"(p));
    return a;
}
__device__ __forceinline__ void cp16(uint32_t d, const void* s, uint32_t sz) {
    asm volatile("{ .reg .u64 g; cvta.to.global.u64 g, %1; cp.async.cg.shared.global [%0], [g], 16, %2; }"
                 :: "r"(d), "l"(s), "r"(sz) : "memory");
}
#define CP_COMMIT() asm volatile("cp.async.commit_group;" ::: "memory")
#define CP_WAIT1()  asm volatile("cp.async.wait_group 1;" ::: "memory")
#define CP_WAIT0()  asm volatile("cp.async.wait_group 0;" ::: "memory")

#define MMA(C_, A_, B_)                                                          \
    asm volatile(                                                                \
        "mma.sync.aligned.m16n8k16.row.col.f32.bf16.bf16.f32 "                   \
        "{%0,%1,%2,%3}, {%4,%5,%6,%7}, {%8,%9}, {%0,%1,%2,%3};\n"                \
        : "+f"(C_[0]), "+f"(C_[1]), "+f"(C_[2]), "+f"(C_[3])                     \
        : "r"(A_[0]), "r"(A_[1]), "r"(A_[2]), "r"(A_[3]), "r"(B_[0]), "r"(B_[1]))

// ---------------- CSR build ----------------
__global__ void k_zero(int* p, int n) {
    int i = blockIdx.x * blockDim.x + threadIdx.x;
    if (i < n) p[i] = 0;
}
__global__ void k_count(const int* __restrict__ dst, int* deg) {
    int e = blockIdx.x * blockDim.x + threadIdx.x;
    if (e < EE) atomicAdd(&deg[dst[e]], 1);
}
__global__ void k_scan(const int* __restrict__ deg, int* off, int* pos) {
    __shared__ int wtot[32];
    int tid = threadIdx.x, lane = tid & 31, w = tid >> 5;
    int running = 0;
    for (int base = 0; base < NN; base += 1024) {
        int i = base + tid;
        int v = (i < NN) ? deg[i] : 0;
        int incl = v;
#pragma unroll
        for (int s = 1; s < 32; s <<= 1) {
            int t = __shfl_up_sync(0xffffffffu, incl, s);
            if (lane >= s) incl += t;
        }
        if (lane == 31) wtot[w] = incl;
        __syncthreads();
        if (tid < 32) {
            int t = wtot[tid];
#pragma unroll
            for (int s = 1; s < 32; s <<= 1) {
                int u = __shfl_up_sync(0xffffffffu, t, s);
                if (tid >= s) t += u;
            }
            wtot[tid] = t;
        }
        __syncthreads();
        int woff = (w == 0) ? 0 : wtot[w - 1];
        int excl = running + woff + incl - v;
        if (i < NN) { off[i] = excl; pos[i] = excl; }
        int tot = wtot[31];
        __syncthreads();
        running += tot;
    }
    if (tid == 0) off[NN] = running;
}
__global__ void k_scatter(const int* __restrict__ src, const int* __restrict__ dst,
                          int* pos, int* csr) {
    int e = blockIdx.x * blockDim.x + threadIdx.x;
    if (e < EE) {
        int p = atomicAdd(&pos[dst[e]], 1);
        csr[p] = src[e];
    }
}

// ---------------- aggregation: fp32 in, split bf16 out ----------------
__device__ __forceinline__ void st_split4(__nv_bfloat16* oh, __nv_bfloat16* ol, float4 a) {
    union { uint2 u; __nv_bfloat16 b[4]; } H, L;
    float f[4] = {a.x, a.y, a.z, a.w};
#pragma unroll
    for (int j = 0; j < 4; j++) {
        __nv_bfloat16 h = __float2bfloat16(f[j]);
        H.b[j] = h;
        L.b[j] = __float2bfloat16(f[j] - __bfloat162float(h));
    }
    *(uint2*)oh = H.u;
    *(uint2*)ol = L.u;
}

__global__ void __launch_bounds__(256) k_agg_split(const float* __restrict__ x,
                                                   const int* __restrict__ off,
                                                   const int* __restrict__ csr,
                                                   __nv_bfloat16* __restrict__ oh,
                                                   __nv_bfloat16* __restrict__ ol) {
    int wid = (blockIdx.x * blockDim.x + threadIdx.x) >> 5;
    int lane = threadIdx.x & 31;
    if (wid >= NN) return;
    const float4* x4 = (const float4*)x;
    size_t rb = (size_t)wid * 64;
    float4 a0 = x4[rb + lane];
    float4 a1 = x4[rb + 32 + lane];
    int s = off[wid], e = off[wid + 1];
    for (int i = s; i < e; i++) {
        size_t ub = (size_t)csr[i] * 64;
        float4 v0 = x4[ub + lane];
        float4 v1 = x4[ub + 32 + lane];
        a0.x += v0.x; a0.y += v0.y; a0.z += v0.z; a0.w += v0.w;
        a1.x += v1.x; a1.y += v1.y; a1.z += v1.z; a1.w += v1.w;
    }
    size_t ob = (size_t)wid * CC;
    st_split4(oh + ob + lane * 4, ol + ob + lane * 4, a0);
    st_split4(oh + ob + 128 + lane * 4, ol + ob + 128 + lane * 4, a1);
}

// ---------------- weight prep: transpose + split ----------------
__global__ void k_wprep(const float* __restrict__ W, __nv_bfloat16* th,
                        __nv_bfloat16* tl, int K, int N) {
    int i = blockIdx.x * blockDim.x + threadIdx.x;
    if (i >= K * N) return;
    int k = i / N, n = i - k * N;
    float v = W[i];
    __nv_bfloat16 h = __float2bfloat16(v);
    th[(size_t)n * K + k] = h;
    tl[(size_t)n * K + k] = __float2bfloat16(v - __bfloat162float(h));
}

// ---------------- mma.sync GEMM, pre-split bf16 inputs, cp.async double buffer --------
// out[M,N] = A[M,K] @ W^T (W given transposed [N,K]); 3-product split accumulation.
// CTA tile 128x128, BK=32, 8 warps as 4x2, warp tile 32x64.
__global__ void __launch_bounds__(256, 2) k_gemm_mma(
    const __nv_bfloat16* __restrict__ Ah, const __nv_bfloat16* __restrict__ Al,
    const __nv_bfloat16* __restrict__ Wh, const __nv_bfloat16* __restrict__ Wl,
    const float* __restrict__ bias,
    float* __restrict__ outF, __nv_bfloat16* __restrict__ outH,
    __nv_bfloat16* __restrict__ outL,
    int M, int K, int N, int relu) {
    extern __shared__ char smem[];
    uint32_t sbase = s2u(smem);
    int tid = threadIdx.x, lane = tid & 31, warp = tid >> 5;
    int g = lane >> 2, tig = lane & 3;
    int wm = warp >> 1, wn = warp & 1;
    int m0 = blockIdx.x * 128, n0 = blockIdx.y * 128;
    const int NS = K >> 5;

    float c[2][8][4];
#pragma unroll
    for (int m = 0; m < 2; m++)
#pragma unroll
        for (int n = 0; n < 8; n++)
#pragma unroll
            for (int i = 0; i < 4; i++) c[m][n][i] = 0.f;

    // stage loader: 2048 16B chunks -> 8 per thread
    auto issue = [&](int s) {
        uint32_t base = sbase + (uint32_t)(s & 1) * STAGE_B;
        int kb = s * 32;
#pragma unroll
        for (int it = 0; it < 8; it++) {
            int ch = tid + it * 256;
            int sel = ch >> 9;                 // 0=Ah 1=Al 2=Bh 3=Bl
            int idx = ch & 511;
            int row = idx >> 2, i = idx & 3;
            uint32_t dstp = base + (uint32_t)sel * MAT_B + (uint32_t)row * 80u + (uint32_t)i * 16u;
            const __nv_bfloat16* gp;
            uint32_t sz = 16;
            if (sel < 2) {
                int gr = m0 + row;
                gp = (sel == 0 ? Ah : Al);
                if (gr < M) gp += (size_t)gr * K + kb + i * 8; else sz = 0;
            } else {
                int gc = n0 + row;
                gp = (sel == 2 ? Wh : Wl);
                if (gc < N) gp += (size_t)gc * K + kb + i * 8; else sz = 0;
            }
            cp16(dstp, gp, sz);
        }
    };

    issue(0);
    CP_COMMIT();
    for (int s = 0; s < NS; s++) {
        if (s + 1 < NS) { issue(s + 1); CP_COMMIT(); CP_WAIT1(); }
        else            { CP_WAIT0(); }
        __syncthreads();

        const __nv_bfloat16* sAh = (const __nv_bfloat16*)(smem + (s & 1) * STAGE_B);
        const __nv_bfloat16* sAl = (const __nv_bfloat16*)(smem + (s & 1) * STAGE_B + MAT_B);
        const __nv_bfloat16* sBh = (const __nv_bfloat16*)(smem + (s & 1) * STAGE_B + 2 * MAT_B);
        const __nv_bfloat16* sBl = (const __nv_bfloat16*)(smem + (s & 1) * STAGE_B + 3 * MAT_B);

#pragma unroll
        for (int ks = 0; ks < 2; ks++) {
            int kb = ks * 16;
            unsigned aH[2][4], aL[2][4];
#pragma unroll
            for (int m = 0; m < 2; m++) {
                int row = wm * 32 + m * 16 + g;
                const __nv_bfloat16* p = &sAh[row * PK + kb + 2 * tig];
                const __nv_bfloat16* q = &sAl[row * PK + kb + 2 * tig];
                aH[m][0] = *(const unsigned*)p;
                aH[m][1] = *(const unsigned*)(p + 8 * PK);
                aH[m][2] = *(const unsigned*)(p + 8);
                aH[m][3] = *(const unsigned*)(p + 8 * PK + 8);
                aL[m][0] = *(const unsigned*)q;
                aL[m][1] = *(const unsigned*)(q + 8 * PK);
                aL[m][2] = *(const unsigned*)(q + 8);
                aL[m][3] = *(const unsigned*)(q + 8 * PK + 8);
            }
#pragma unroll
            for (int n = 0; n < 8; n++) {
                int col = wn * 64 + n * 8 + g;
                const __nv_bfloat16* p = &sBh[col * PK + kb + 2 * tig];
                const __nv_bfloat16* q = &sBl[col * PK + kb + 2 * tig];
                unsigned bH[2], bL[2];
                bH[0] = *(const unsigned*)p;
                bH[1] = *(const unsigned*)(p + 8);
                bL[0] = *(const unsigned*)q;
                bL[1] = *(const unsigned*)(q + 8);
#pragma unroll
                for (int m = 0; m < 2; m++) {
                    MMA(c[m][n], aH[m], bH);
                    MMA(c[m][n], aH[m], bL);
                    MMA(c[m][n], aL[m], bH);
                }
            }
        }
        __syncthreads();
    }

    // epilogue: bias + relu, write fp32 or split hi/lo
#pragma unroll
    for (int m = 0; m < 2; m++) {
        int row = m0 + wm * 32 + m * 16 + g;
#pragma unroll
        for (int n = 0; n < 8; n++) {
            int col = n0 + wn * 64 + n * 8 + 2 * tig;
            if (col >= N) continue;
            float b0 = bias[col], b1 = bias[col + 1];
            float v0 = c[m][n][0] + b0, v1 = c[m][n][1] + b1;
            float v2 = c[m][n][2] + b0, v3 = c[m][n][3] + b1;
            if (relu) {
                v0 = fmaxf(v0, 0.f); v1 = fmaxf(v1, 0.f);
                v2 = fmaxf(v2, 0.f); v3 = fmaxf(v3, 0.f);
            }
            if (outF) {
                if (row < M) *(float2*)(outF + (size_t)row * N + col) = make_float2(v0, v1);
                if (row + 8 < M) *(float2*)(outF + (size_t)(row + 8) * N + col) = make_float2(v2, v3);
            } else {
                __nv_bfloat16 h0 = __float2bfloat16(v0), h1 = __float2bfloat16(v1);
                __nv_bfloat16 h2 = __float2bfloat16(v2), h3 = __float2bfloat16(v3);
                __nv_bfloat16 l0 = __float2bfloat16(v0 - __bfloat162float(h0));
                __nv_bfloat16 l1 = __float2bfloat16(v1 - __bfloat162float(h1));
                __nv_bfloat16 l2 = __float2bfloat16(v2 - __bfloat162float(h2));
                __nv_bfloat16 l3 = __float2bfloat16(v3 - __bfloat162float(h3));
                if (row < M) {
                    *(__nv_bfloat162*)(outH + (size_t)row * N + col) = __halves2bfloat162(h0, h1);
                    *(__nv_bfloat162*)(outL + (size_t)row * N + col) = __halves2bfloat162(l0, l1);
                }
                if (row + 8 < M) {
                    *(__nv_bfloat162*)(outH + (size_t)(row + 8) * N + col) = __halves2bfloat162(h2, h3);
                    *(__nv_bfloat162*)(outL + (size_t)(row + 8) * N + col) = __halves2bfloat162(l2, l3);
                }
            }
        }
    }
}

// ---------------- launch ----------------
extern "C" void kernel_launch(void* const* d_in, const int* in_sizes, int n_in,
                              void* d_out, int out_size) {
    const float* x   = (const float*)d_in[0];
    const int*   src = (const int*)d_in[1];
    const int*   dst = (const int*)d_in[2];
    const float* W1s = (const float*)d_in[3];
    const float* b1s = (const float*)d_in[4];
    const float* W2s = (const float*)d_in[5];
    const float* b2s = (const float*)d_in[6];
    const float* W3s = (const float*)d_in[7];
    const float* b3s = (const float*)d_in[8];
    const float* cW1 = (const float*)d_in[9];
    const float* cb1 = (const float*)d_in[10];
    const float* cW2 = (const float*)d_in[11];
    const float* cb2 = (const float*)d_in[12];
    const float* cW3 = (const float*)d_in[13];
    const float* cb3 = (const float*)d_in[14];
    float* out = (float*)d_out;

    float* s0;
    __nv_bfloat16 *pAh, *pAl, *pBh, *pBl, *wh, *wl;
    int *deg, *off, *pos, *csr;
    cudaGetSymbolAddress((void**)&s0, g_s0);
    cudaGetSymbolAddress((void**)&pAh, g_pAh);
    cudaGetSymbolAddress((void**)&pAl, g_pAl);
    cudaGetSymbolAddress((void**)&pBh, g_pBh);
    cudaGetSymbolAddress((void**)&pBl, g_pBl);
    cudaGetSymbolAddress((void**)&wh, g_wh);
    cudaGetSymbolAddress((void**)&wl, g_wl);
    cudaGetSymbolAddress((void**)&deg, g_deg);
    cudaGetSymbolAddress((void**)&off, g_off);
    cudaGetSymbolAddress((void**)&pos, g_pos);
    cudaGetSymbolAddress((void**)&csr, g_csr);

    const int SMEM = 2 * (int)STAGE_B;  // 81920
    static int attr_done = 0;
    if (!attr_done) {
        cudaFuncSetAttribute(k_gemm_mma, cudaFuncAttributeMaxDynamicSharedMemorySize, SMEM);
        attr_done = 1;
    }

    // weight prep (transpose + split, once per call)
    for (int l = 0; l < 3; l++) {
        k_wprep<<<256, 256>>>(W1s + (size_t)l * 65536, wh + WOFF_INNER(l, 0), wl + WOFF_INNER(l, 0), 256, 256);
        k_wprep<<<256, 256>>>(W2s + (size_t)l * 65536, wh + WOFF_INNER(l, 1), wl + WOFF_INNER(l, 1), 256, 256);
        k_wprep<<<256, 256>>>(W3s + (size_t)l * 65536, wh + WOFF_INNER(l, 2), wl + WOFF_INNER(l, 2), 256, 256);
    }
    k_wprep<<<256, 256>>>(cW1, wh + WOFF_CW1, wl + WOFF_CW1, 256, 256);
    k_wprep<<<64, 256>>>(cW2, wh + WOFF_CW2, wl + WOFF_CW2, 256, 64);
    k_wprep<<<64, 256>>>(cW3, wh + WOFF_CW3, wl + WOFF_CW3, 64, 256);

    // CSR build
    k_zero<<<(NN + 255) / 256, 256>>>(deg, NN);
    k_count<<<(EE + 255) / 256, 256>>>(dst, deg);
    k_scan<<<1, 1024>>>(deg, off, pos);
    k_scatter<<<(EE + 255) / 256, 256>>>(src, dst, pos, csr);

    const int GB = (NN + 127) / 128;  // 391
    const int aggBlocks = (NN + 7) / 8;
    dim3 g256(GB, 2), g64(GB, 1);

    k_agg_split<<<aggBlocks, 256>>>(x, off, csr, pAh, pAl);
    for (int l = 0; l < 3; l++) {
        k_gemm_mma<<<g256, 256, SMEM>>>(pAh, pAl, wh + WOFF_INNER(l, 0), wl + WOFF_INNER(l, 0),
                                        b1s + (size_t)l * CC, nullptr, pBh, pBl, NN, 256, 256, 1);
        k_gemm_mma<<<g256, 256, SMEM>>>(pBh, pBl, wh + WOFF_INNER(l, 1), wl + WOFF_INNER(l, 1),
                                        b2s + (size_t)l * CC, nullptr, pAh, pAl, NN, 256, 256, 1);
        k_gemm_mma<<<g256, 256, SMEM>>>(pAh, pAl, wh + WOFF_INNER(l, 2), wl + WOFF_INNER(l, 2),
                                        b3s + (size_t)l * CC, s0, nullptr, nullptr, NN, 256, 256, 0);
        k_agg_split<<<aggBlocks, 256>>>(s0, off, csr, pAh, pAl);
    }
    k_gemm_mma<<<g256, 256, SMEM>>>(pAh, pAl, wh + WOFF_CW1, wl + WOFF_CW1,
                                    cb1, nullptr, pBh, pBl, NN, 256, 256, 1);
    k_gemm_mma<<<g64, 256, SMEM>>>(pBh, pBl, wh + WOFF_CW2, wl + WOFF_CW2,
                                   cb2, nullptr, pAh, pAl, NN, 256, 64, 1);
    k_gemm_mma<<<g256, 256, SMEM>>>(pAh, pAl, wh + WOFF_CW3, wl + WOFF_CW3,
                                    cb3, out, nullptr, nullptr, NN, 64, 256, 0);
}

// round 4
// speedup vs baseline: 1.5152x; 1.0758x over previous
#include <cuda_runtime.h>
#include <cuda_bf16.h>
#include <cstdint>

#define NN 50000
#define EE 800000
#define CC 256

#define PK 40            // padded bf16 row stride in smem (conflict-free for LDS + LDSM)
#define MAT_B 10240u     // one 128xPK bf16 matrix = 128*40*2 bytes
#define STAGE_B 40960u   // Ah+Al+Bh+Bl per stage

// ---------------- scratch (device globals; no allocations) ----------------
__device__ __align__(16) float g_s0[(size_t)NN * CC];
__device__ __align__(16) __nv_bfloat16 g_pAh[(size_t)NN * CC];
__device__ __align__(16) __nv_bfloat16 g_pAl[(size_t)NN * CC];
__device__ __align__(16) __nv_bfloat16 g_pBh[(size_t)NN * CC];
__device__ __align__(16) __nv_bfloat16 g_pBl[(size_t)NN * CC];
#define WOFF_INNER(l, j) ((size_t)((l)*3 + (j)) * 65536)
#define WOFF_CW1 589824
#define WOFF_CW2 655360
#define WOFF_CW3 671744
#define WTOT 688128
__device__ __align__(16) __nv_bfloat16 g_wh[WTOT];
__device__ __align__(16) __nv_bfloat16 g_wl[WTOT];
__device__ int g_deg[NN];
__device__ int g_off[NN + 1];
__device__ int g_pos[NN];
__device__ int g_csr[EE];

// ---------------- PTX helpers ----------------
__device__ __forceinline__ uint32_t s2u(const void* p) {
    uint32_t a;
    asm("{ .reg .u64 t; cvta.to.shared.u64 t, %1; cvt.u32.u64 %0, t; }" : "=r"(a) : "l"(p));
    return a;
}
__device__ __forceinline__ void cp16(uint32_t d, const void* s, uint32_t sz) {
    asm volatile("{ .reg .u64 g; cvta.to.global.u64 g, %1; cp.async.cg.shared.global [%0], [g], 16, %2; }"
                 :: "r"(d), "l"(s), "r"(sz) : "memory");
}
#define CP_COMMIT() asm volatile("cp.async.commit_group;" ::: "memory")
#define CP_WAIT1()  asm volatile("cp.async.wait_group 1;" ::: "memory")
#define CP_WAIT0()  asm volatile("cp.async.wait_group 0;" ::: "memory")

#define MMA(C_, A_, B0_, B1_)                                                    \
    asm volatile(                                                                \
        "mma.sync.aligned.m16n8k16.row.col.f32.bf16.bf16.f32 "                   \
        "{%0,%1,%2,%3}, {%4,%5,%6,%7}, {%8,%9}, {%0,%1,%2,%3};\n"                \
        : "+f"(C_[0]), "+f"(C_[1]), "+f"(C_[2]), "+f"(C_[3])                     \
        : "r"(A_[0]), "r"(A_[1]), "r"(A_[2]), "r"(A_[3]), "r"(B0_), "r"(B1_))

#define LDSM4(R_, a)                                                             \
    asm volatile("ldmatrix.sync.aligned.m8n8.x4.shared.b16 {%0,%1,%2,%3}, [%4];" \
                 : "=r"((R_)[0]), "=r"((R_)[1]), "=r"((R_)[2]), "=r"((R_)[3])    \
                 : "r"(a))

// ---------------- CSR build ----------------
__global__ void k_zero(int* p, int n) {
    int i = blockIdx.x * blockDim.x + threadIdx.x;
    if (i < n) p[i] = 0;
}
__global__ void k_count(const int* __restrict__ dst, int* deg) {
    int e = blockIdx.x * blockDim.x + threadIdx.x;
    if (e < EE) atomicAdd(&deg[dst[e]], 1);
}
__global__ void k_scan(const int* __restrict__ deg, int* off, int* pos) {
    __shared__ int wtot[32];
    int tid = threadIdx.x, lane = tid & 31, w = tid >> 5;
    int running = 0;
    for (int base = 0; base < NN; base += 1024) {
        int i = base + tid;
        int v = (i < NN) ? deg[i] : 0;
        int incl = v;
#pragma unroll
        for (int s = 1; s < 32; s <<= 1) {
            int t = __shfl_up_sync(0xffffffffu, incl, s);
            if (lane >= s) incl += t;
        }
        if (lane == 31) wtot[w] = incl;
        __syncthreads();
        if (tid < 32) {
            int t = wtot[tid];
#pragma unroll
            for (int s = 1; s < 32; s <<= 1) {
                int u = __shfl_up_sync(0xffffffffu, t, s);
                if (tid >= s) t += u;
            }
            wtot[tid] = t;
        }
        __syncthreads();
        int woff = (w == 0) ? 0 : wtot[w - 1];
        int excl = running + woff + incl - v;
        if (i < NN) { off[i] = excl; pos[i] = excl; }
        int tot = wtot[31];
        __syncthreads();
        running += tot;
    }
    if (tid == 0) off[NN] = running;
}
__global__ void k_scatter(const int* __restrict__ src, const int* __restrict__ dst,
                          int* pos, int* csr) {
    int e = blockIdx.x * blockDim.x + threadIdx.x;
    if (e < EE) {
        int p = atomicAdd(&pos[dst[e]], 1);
        csr[p] = src[e];
    }
}

// ---------------- aggregation: fp32 in, split bf16 out ----------------
__device__ __forceinline__ void st_split4(__nv_bfloat16* oh, __nv_bfloat16* ol, float4 a) {
    union { uint2 u; __nv_bfloat16 b[4]; } H, L;
    float f[4] = {a.x, a.y, a.z, a.w};
#pragma unroll
    for (int j = 0; j < 4; j++) {
        __nv_bfloat16 h = __float2bfloat16(f[j]);
        H.b[j] = h;
        L.b[j] = __float2bfloat16(f[j] - __bfloat162float(h));
    }
    *(uint2*)oh = H.u;
    *(uint2*)ol = L.u;
}

__global__ void __launch_bounds__(256) k_agg_split(const float* __restrict__ x,
                                                   const int* __restrict__ off,
                                                   const int* __restrict__ csr,
                                                   __nv_bfloat16* __restrict__ oh,
                                                   __nv_bfloat16* __restrict__ ol) {
    int wid = (blockIdx.x * blockDim.x + threadIdx.x) >> 5;
    int lane = threadIdx.x & 31;
    if (wid >= NN) return;
    const float4* x4 = (const float4*)x;
    size_t rb = (size_t)wid * 64;
    float4 a0 = x4[rb + lane];
    float4 a1 = x4[rb + 32 + lane];
    int s = off[wid], e = off[wid + 1];
    for (int i = s; i < e; i++) {
        size_t ub = (size_t)csr[i] * 64;
        float4 v0 = x4[ub + lane];
        float4 v1 = x4[ub + 32 + lane];
        a0.x += v0.x; a0.y += v0.y; a0.z += v0.z; a0.w += v0.w;
        a1.x += v1.x; a1.y += v1.y; a1.z += v1.z; a1.w += v1.w;
    }
    size_t ob = (size_t)wid * CC;
    st_split4(oh + ob + lane * 4, ol + ob + lane * 4, a0);
    st_split4(oh + ob + 128 + lane * 4, ol + ob + 128 + lane * 4, a1);
}

// ---------------- fused weight prep: all 12 matrices in one launch ----------------
__global__ void k_wprep_all(const float* __restrict__ W1s, const float* __restrict__ W2s,
                            const float* __restrict__ W3s, const float* __restrict__ cW1,
                            const float* __restrict__ cW2, const float* __restrict__ cW3,
                            __nv_bfloat16* __restrict__ th, __nv_bfloat16* __restrict__ tl) {
    int i = blockIdx.x * blockDim.x + threadIdx.x;
    if (i >= WTOT) return;
    const float* src;
    size_t dsto;
    int K, N, r;
    if (i < 589824) {
        int m = i / 65536;
        r = i - m * 65536;
        int l = m / 3, j = m - l * 3;
        src = (j == 0 ? W1s : j == 1 ? W2s : W3s) + (size_t)l * 65536;
        dsto = (size_t)m * 65536;
        K = 256; N = 256;
    } else if (i < 655360) {
        r = i - 589824; src = cW1; dsto = WOFF_CW1; K = 256; N = 256;
    } else if (i < 671744) {
        r = i - 655360; src = cW2; dsto = WOFF_CW2; K = 256; N = 64;
    } else {
        r = i - 671744; src = cW3; dsto = WOFF_CW3; K = 64; N = 256;
    }
    int k = r / N, n = r - k * N;
    float v = src[r];
    __nv_bfloat16 h = __float2bfloat16(v);
    size_t d = dsto + (size_t)n * K + k;
    th[d] = h;
    tl[d] = __float2bfloat16(v - __bfloat162float(h));
}

// ---------------- mma.sync GEMM: ldmatrix fragments, cp.async double buffer ----------
// out[M,N] = A[M,K] @ W^T (W transposed [N,K]); 3-product split accumulation.
// CTA 128x128, BK=32, 8 warps as 4x2, warp tile 32x64.
__global__ void __launch_bounds__(256, 2) k_gemm_mma(
    const __nv_bfloat16* __restrict__ Ah, const __nv_bfloat16* __restrict__ Al,
    const __nv_bfloat16* __restrict__ Wh, const __nv_bfloat16* __restrict__ Wl,
    const float* __restrict__ bias,
    float* __restrict__ outF, __nv_bfloat16* __restrict__ outH,
    __nv_bfloat16* __restrict__ outL,
    int M, int K, int N, int relu) {
    extern __shared__ char smem[];
    uint32_t sbase = s2u(smem);
    int tid = threadIdx.x, lane = tid & 31, warp = tid >> 5;
    int g = lane >> 2, tig = lane & 3;
    int wm = warp >> 1, wn = warp & 1;
    int m0 = blockIdx.x * 128, n0 = blockIdx.y * 128;
    const int NS = K >> 5;

    // per-lane ldmatrix offsets (bytes, relative to matrix base, k=0)
    // A x4: M0 rows+0..7 klo | M1 rows+8..15 klo | M2 rows+0..7 khi | M3 rows+8 khi
    uint32_t aOff = (uint32_t)(((wm * 32 + (lane & 7) + ((lane >> 3) & 1) * 8) * PK
                               + ((lane >> 4) & 1) * 8) * 2);
    // B x4: M0 n+0..7 klo | M1 n+0..7 khi | M2 n+8..15 klo | M3 n+8..15 khi
    uint32_t bOff = (uint32_t)(((wn * 64 + (lane & 7) + ((lane >> 4) & 1) * 8) * PK
                               + ((lane >> 3) & 1) * 8) * 2);

    float c[2][8][4];
#pragma unroll
    for (int m = 0; m < 2; m++)
#pragma unroll
        for (int n = 0; n < 8; n++)
#pragma unroll
            for (int i = 0; i < 4; i++) c[m][n][i] = 0.f;

    auto issue = [&](int s) {
        uint32_t base = sbase + (uint32_t)(s & 1) * STAGE_B;
        int kb = s * 32;
#pragma unroll
        for (int it = 0; it < 8; it++) {
            int ch = tid + it * 256;
            int sel = ch >> 9;                 // 0=Ah 1=Al 2=Bh 3=Bl
            int idx = ch & 511;
            int row = idx >> 2, i = idx & 3;
            uint32_t dstp = base + (uint32_t)sel * MAT_B + (uint32_t)row * 80u + (uint32_t)i * 16u;
            const __nv_bfloat16* gp;
            uint32_t sz = 16;
            if (sel < 2) {
                int gr = m0 + row;
                gp = (sel == 0 ? Ah : Al);
                if (gr < M) gp += (size_t)gr * K + kb + i * 8; else sz = 0;
            } else {
                int gc = n0 + row;
                gp = (sel == 2 ? Wh : Wl);
                if (gc < N) gp += (size_t)gc * K + kb + i * 8; else sz = 0;
            }
            cp16(dstp, gp, sz);
        }
    };

    issue(0);
    CP_COMMIT();
    for (int s = 0; s < NS; s++) {
        if (s + 1 < NS) { issue(s + 1); CP_COMMIT(); CP_WAIT1(); }
        else            { CP_WAIT0(); }
        __syncthreads();

        uint32_t stg = sbase + (uint32_t)(s & 1) * STAGE_B;
        uint32_t aHb = stg + aOff;
        uint32_t aLb = stg + MAT_B + aOff;
        uint32_t bHb = stg + 2u * MAT_B + bOff;
        uint32_t bLb = stg + 3u * MAT_B + bOff;

#pragma unroll
        for (int ks = 0; ks < 2; ks++) {
            uint32_t ko = (uint32_t)(ks * 16 * 2);
            unsigned aH[2][4], aL[2][4];
#pragma unroll
            for (int m = 0; m < 2; m++) {
                uint32_t mo = (uint32_t)(m * 16 * PK * 2) + ko;
                LDSM4(aH[m], aHb + mo);
                LDSM4(aL[m], aLb + mo);
            }
#pragma unroll
            for (int p = 0; p < 4; p++) {
                uint32_t po = (uint32_t)(p * 16 * PK * 2) + ko;
                unsigned bH[4], bL[4];
                LDSM4(bH, bHb + po);   // bH[0],bH[1]=ntile 2p; bH[2],bH[3]=ntile 2p+1
                LDSM4(bL, bLb + po);
#pragma unroll
                for (int m = 0; m < 2; m++) {
                    MMA(c[m][2 * p],     aH[m], bH[0], bH[1]);
                    MMA(c[m][2 * p],     aH[m], bL[0], bL[1]);
                    MMA(c[m][2 * p],     aL[m], bH[0], bH[1]);
                    MMA(c[m][2 * p + 1], aH[m], bH[2], bH[3]);
                    MMA(c[m][2 * p + 1], aH[m], bL[2], bL[3]);
                    MMA(c[m][2 * p + 1], aL[m], bH[2], bH[3]);
                }
            }
        }
        __syncthreads();
    }

    // epilogue: bias + relu, write fp32 or split hi/lo
#pragma unroll
    for (int m = 0; m < 2; m++) {
        int row = m0 + wm * 32 + m * 16 + g;
#pragma unroll
        for (int n = 0; n < 8; n++) {
            int col = n0 + wn * 64 + n * 8 + 2 * tig;
            if (col >= N) continue;
            float b0 = bias[col], b1 = bias[col + 1];
            float v0 = c[m][n][0] + b0, v1 = c[m][n][1] + b1;
            float v2 = c[m][n][2] + b0, v3 = c[m][n][3] + b1;
            if (relu) {
                v0 = fmaxf(v0, 0.f); v1 = fmaxf(v1, 0.f);
                v2 = fmaxf(v2, 0.f); v3 = fmaxf(v3, 0.f);
            }
            if (outF) {
                if (row < M) *(float2*)(outF + (size_t)row * N + col) = make_float2(v0, v1);
                if (row + 8 < M) *(float2*)(outF + (size_t)(row + 8) * N + col) = make_float2(v2, v3);
            } else {
                __nv_bfloat16 h0 = __float2bfloat16(v0), h1 = __float2bfloat16(v1);
                __nv_bfloat16 h2 = __float2bfloat16(v2), h3 = __float2bfloat16(v3);
                __nv_bfloat16 l0 = __float2bfloat16(v0 - __bfloat162float(h0));
                __nv_bfloat16 l1 = __float2bfloat16(v1 - __bfloat162float(h1));
                __nv_bfloat16 l2 = __float2bfloat16(v2 - __bfloat162float(h2));
                __nv_bfloat16 l3 = __float2bfloat16(v3 - __bfloat162float(h3));
                if (row < M) {
                    *(__nv_bfloat162*)(outH + (size_t)row * N + col) = __halves2bfloat162(h0, h1);
                    *(__nv_bfloat162*)(outL + (size_t)row * N + col) = __halves2bfloat162(l0, l1);
                }
                if (row + 8 < M) {
                    *(__nv_bfloat162*)(outH + (size_t)(row + 8) * N + col) = __halves2bfloat162(h2, h3);
                    *(__nv_bfloat162*)(outL + (size_t)(row + 8) * N + col) = __halves2bfloat162(l2, l3);
                }
            }
        }
    }
}

// ---------------- launch ----------------
extern "C" void kernel_launch(void* const* d_in, const int* in_sizes, int n_in,
                              void* d_out, int out_size) {
    const float* x   = (const float*)d_in[0];
    const int*   src = (const int*)d_in[1];
    const int*   dst = (const int*)d_in[2];
    const float* W1s = (const float*)d_in[3];
    const float* b1s = (const float*)d_in[4];
    const float* W2s = (const float*)d_in[5];
    const float* b2s = (const float*)d_in[6];
    const float* W3s = (const float*)d_in[7];
    const float* b3s = (const float*)d_in[8];
    const float* cW1 = (const float*)d_in[9];
    const float* cb1 = (const float*)d_in[10];
    const float* cW2 = (const float*)d_in[11];
    const float* cb2 = (const float*)d_in[12];
    const float* cW3 = (const float*)d_in[13];
    const float* cb3 = (const float*)d_in[14];
    float* out = (float*)d_out;

    float* s0;
    __nv_bfloat16 *pAh, *pAl, *pBh, *pBl, *wh, *wl;
    int *deg, *off, *pos, *csr;
    cudaGetSymbolAddress((void**)&s0, g_s0);
    cudaGetSymbolAddress((void**)&pAh, g_pAh);
    cudaGetSymbolAddress((void**)&pAl, g_pAl);
    cudaGetSymbolAddress((void**)&pBh, g_pBh);
    cudaGetSymbolAddress((void**)&pBl, g_pBl);
    cudaGetSymbolAddress((void**)&wh, g_wh);
    cudaGetSymbolAddress((void**)&wl, g_wl);
    cudaGetSymbolAddress((void**)&deg, g_deg);
    cudaGetSymbolAddress((void**)&off, g_off);
    cudaGetSymbolAddress((void**)&pos, g_pos);
    cudaGetSymbolAddress((void**)&csr, g_csr);

    const int SMEM = 2 * (int)STAGE_B;  // 81920
    cudaFuncSetAttribute(k_gemm_mma, cudaFuncAttributeMaxDynamicSharedMemorySize, SMEM);

    // weight prep (one fused launch)
    k_wprep_all<<<(WTOT + 255) / 256, 256>>>(W1s, W2s, W3s, cW1, cW2, cW3, wh, wl);

    // CSR build
    k_zero<<<(NN + 255) / 256, 256>>>(deg, NN);
    k_count<<<(EE + 255) / 256, 256>>>(dst, deg);
    k_scan<<<1, 1024>>>(deg, off, pos);
    k_scatter<<<(EE + 255) / 256, 256>>>(src, dst, pos, csr);

    const int GB = (NN + 127) / 128;  // 391
    const int aggBlocks = (NN + 7) / 8;
    dim3 g256(GB, 2), g64(GB, 1);

    k_agg_split<<<aggBlocks, 256>>>(x, off, csr, pAh, pAl);
    for (int l = 0; l < 3; l++) {
        k_gemm_mma<<<g256, 256, SMEM>>>(pAh, pAl, wh + WOFF_INNER(l, 0), wl + WOFF_INNER(l, 0),
                                        b1s + (size_t)l * CC, nullptr, pBh, pBl, NN, 256, 256, 1);
        k_gemm_mma<<<g256, 256, SMEM>>>(pBh, pBl, wh + WOFF_INNER(l, 1), wl + WOFF_INNER(l, 1),
                                        b2s + (size_t)l * CC, nullptr, pAh, pAl, NN, 256, 256, 1);
        k_gemm_mma<<<g256, 256, SMEM>>>(pAh, pAl, wh + WOFF_INNER(l, 2), wl + WOFF_INNER(l, 2),
                                        b3s + (size_t)l * CC, s0, nullptr, nullptr, NN, 256, 256, 0);
        k_agg_split<<<aggBlocks, 256>>>(s0, off, csr, pAh, pAl);
    }
    k_gemm_mma<<<g256, 256, SMEM>>>(pAh, pAl, wh + WOFF_CW1, wl + WOFF_CW1,
                                    cb1, nullptr, pBh, pBl, NN, 256, 256, 1);
    k_gemm_mma<<<g64, 256, SMEM>>>(pBh, pBl, wh + WOFF_CW2, wl + WOFF_CW2,
                                   cb2, nullptr, pAh, pAl, NN, 256, 64, 1);
    k_gemm_mma<<<g256, 256, SMEM>>>(pAh, pAl, wh + WOFF_CW3, wl + WOFF_CW3,
                                    cb3, out, nullptr, nullptr, NN, 64, 256, 0);
}

// round 5
// speedup vs baseline: 1.5827x; 1.0446x over previous
#include <cuda_runtime.h>
#include <cuda_bf16.h>
#include <cstdint>

#define NN 50000
#define EE 800000
#define CC 256

#define PK 40            // padded bf16 row stride in smem (conflict-free for LDS + LDSM)
#define MAT_B 10240u     // one 128xPK bf16 matrix = 128*40*2 bytes
#define STAGE_B 40960u   // Ah+Al+Bh+Bl per stage
#define NB_SCAN 49       // ceil(NN/1024)

// ---------------- scratch (device globals; no allocations) ----------------
__device__ __align__(16) float g_s0[(size_t)NN * CC];
__device__ __align__(16) __nv_bfloat16 g_pAh[(size_t)NN * CC];
__device__ __align__(16) __nv_bfloat16 g_pAl[(size_t)NN * CC];
__device__ __align__(16) __nv_bfloat16 g_pBh[(size_t)NN * CC];
__device__ __align__(16) __nv_bfloat16 g_pBl[(size_t)NN * CC];
#define WOFF_INNER(l, j) ((size_t)((l)*3 + (j)) * 65536)
#define WOFF_CW1 589824
#define WOFF_CW2 655360
#define WOFF_CW3 671744
#define WTOT 688128
__device__ __align__(16) __nv_bfloat16 g_wh[WTOT];
__device__ __align__(16) __nv_bfloat16 g_wl[WTOT];
__device__ int g_deg[NN];
__device__ int g_off[NN + 1];
__device__ int g_pos[NN];
__device__ int g_csr[EE];
__device__ int g_bsum[64];

// ---------------- PTX helpers ----------------
__device__ __forceinline__ uint32_t s2u(const void* p) {
    uint32_t a;
    asm("{ .reg .u64 t; cvta.to.shared.u64 t, %1; cvt.u32.u64 %0, t; }" : "=r"(a) : "l"(p));
    return a;
}
__device__ __forceinline__ void cp16(uint32_t d, const void* s, uint32_t sz) {
    asm volatile("{ .reg .u64 g; cvta.to.global.u64 g, %1; cp.async.cg.shared.global [%0], [g], 16, %2; }"
                 :: "r"(d), "l"(s), "r"(sz) : "memory");
}
#define CP_COMMIT() asm volatile("cp.async.commit_group;" ::: "memory")
#define CP_WAIT1()  asm volatile("cp.async.wait_group 1;" ::: "memory")
#define CP_WAIT0()  asm volatile("cp.async.wait_group 0;" ::: "memory")

#define MMA(C_, A_, B0_, B1_)                                                    \
    asm volatile(                                                                \
        "mma.sync.aligned.m16n8k16.row.col.f32.bf16.bf16.f32 "                   \
        "{%0,%1,%2,%3}, {%4,%5,%6,%7}, {%8,%9}, {%0,%1,%2,%3};\n"                \
        : "+f"(C_[0]), "+f"(C_[1]), "+f"(C_[2]), "+f"(C_[3])                     \
        : "r"(A_[0]), "r"(A_[1]), "r"(A_[2]), "r"(A_[3]), "r"(B0_), "r"(B1_))

#define LDSM4(R_, a)                                                             \
    asm volatile("ldmatrix.sync.aligned.m8n8.x4.shared.b16 {%0,%1,%2,%3}, [%4];" \
                 : "=r"((R_)[0]), "=r"((R_)[1]), "=r"((R_)[2]), "=r"((R_)[3])    \
                 : "r"(a))

// ---------------- CSR build ----------------
__global__ void k_zero(int* p, int n) {
    int i = blockIdx.x * blockDim.x + threadIdx.x;
    if (i < n) p[i] = 0;
}
__global__ void k_count(const int* __restrict__ dst, int* deg) {
    int e = blockIdx.x * blockDim.x + threadIdx.x;
    if (e < EE) atomicAdd(&deg[dst[e]], 1);
}
// phase 1: per-1024-block local exclusive scan; block totals to bsum
__global__ void __launch_bounds__(1024) k_scan1(const int* __restrict__ deg,
                                                int* __restrict__ off,
                                                int* __restrict__ bsum) {
    __shared__ int wtot[32];
    int tid = threadIdx.x, lane = tid & 31, w = tid >> 5;
    int i = blockIdx.x * 1024 + tid;
    int v = (i < NN) ? deg[i] : 0;
    int incl = v;
#pragma unroll
    for (int s = 1; s < 32; s <<= 1) {
        int t = __shfl_up_sync(0xffffffffu, incl, s);
        if (lane >= s) incl += t;
    }
    if (lane == 31) wtot[w] = incl;
    __syncthreads();
    if (tid < 32) {
        int t = wtot[tid];
#pragma unroll
        for (int s = 1; s < 32; s <<= 1) {
            int u = __shfl_up_sync(0xffffffffu, t, s);
            if (tid >= s) t += u;
        }
        wtot[tid] = t;
    }
    __syncthreads();
    int excl = ((w == 0) ? 0 : wtot[w - 1]) + incl - v;
    if (i < NN) off[i] = excl;
    if (tid == 0) bsum[blockIdx.x] = wtot[31];
}
// phase 2: scan the 49 block sums (exclusive, in place); write total to off[NN]
__global__ void __launch_bounds__(64) k_scan2(int* __restrict__ bsum, int* __restrict__ off) {
    __shared__ int s[64];
    int tid = threadIdx.x;
    int v = (tid < NB_SCAN) ? bsum[tid] : 0;
    s[tid] = v;
    __syncthreads();
#pragma unroll
    for (int d = 1; d < 64; d <<= 1) {
        int t = (tid >= d) ? s[tid - d] : 0;
        __syncthreads();
        s[tid] += t;
        __syncthreads();
    }
    if (tid < NB_SCAN) bsum[tid] = s[tid] - v;      // exclusive base
    if (tid == NB_SCAN - 1) off[NN] = s[tid];       // grand total
}
// phase 3: add block base; replicate to pos
__global__ void k_scan3(int* __restrict__ off, int* __restrict__ pos,
                        const int* __restrict__ bsum) {
    int i = blockIdx.x * blockDim.x + threadIdx.x;
    if (i < NN) {
        int o = off[i] + bsum[i >> 10];
        off[i] = o;
        pos[i] = o;
    }
}
__global__ void k_scatter(const int* __restrict__ src, const int* __restrict__ dst,
                          int* pos, int* csr) {
    int e = blockIdx.x * blockDim.x + threadIdx.x;
    if (e < EE) {
        int p = atomicAdd(&pos[dst[e]], 1);
        csr[p] = src[e];
    }
}

// ---------------- aggregation: fp32 in, split bf16 out ----------------
__device__ __forceinline__ void st_split4(__nv_bfloat16* oh, __nv_bfloat16* ol, float4 a) {
    union { uint2 u; __nv_bfloat16 b[4]; } H, L;
    float f[4] = {a.x, a.y, a.z, a.w};
#pragma unroll
    for (int j = 0; j < 4; j++) {
        __nv_bfloat16 h = __float2bfloat16(f[j]);
        H.b[j] = h;
        L.b[j] = __float2bfloat16(f[j] - __bfloat162float(h));
    }
    *(uint2*)oh = H.u;
    *(uint2*)ol = L.u;
}

__global__ void __launch_bounds__(256) k_agg_split(const float* __restrict__ x,
                                                   const int* __restrict__ off,
                                                   const int* __restrict__ csr,
                                                   __nv_bfloat16* __restrict__ oh,
                                                   __nv_bfloat16* __restrict__ ol) {
    int wid = (blockIdx.x * blockDim.x + threadIdx.x) >> 5;
    int lane = threadIdx.x & 31;
    if (wid >= NN) return;
    const float4* x4 = (const float4*)x;
    size_t rb = (size_t)wid * 64;
    float4 a0 = x4[rb + lane];
    float4 a1 = x4[rb + 32 + lane];
    float4 b0 = make_float4(0.f, 0.f, 0.f, 0.f);
    float4 b1 = make_float4(0.f, 0.f, 0.f, 0.f);
    int s = off[wid], e = off[wid + 1];
    int i = s;
    for (; i + 1 < e; i += 2) {   // two independent accumulation chains -> MLP 4
        size_t u0 = (size_t)csr[i] * 64;
        size_t u1 = (size_t)csr[i + 1] * 64;
        float4 v0 = x4[u0 + lane];
        float4 v1 = x4[u0 + 32 + lane];
        float4 w0 = x4[u1 + lane];
        float4 w1 = x4[u1 + 32 + lane];
        a0.x += v0.x; a0.y += v0.y; a0.z += v0.z; a0.w += v0.w;
        a1.x += v1.x; a1.y += v1.y; a1.z += v1.z; a1.w += v1.w;
        b0.x += w0.x; b0.y += w0.y; b0.z += w0.z; b0.w += w0.w;
        b1.x += w1.x; b1.y += w1.y; b1.z += w1.z; b1.w += w1.w;
    }
    if (i < e) {
        size_t ub = (size_t)csr[i] * 64;
        float4 v0 = x4[ub + lane];
        float4 v1 = x4[ub + 32 + lane];
        a0.x += v0.x; a0.y += v0.y; a0.z += v0.z; a0.w += v0.w;
        a1.x += v1.x; a1.y += v1.y; a1.z += v1.z; a1.w += v1.w;
    }
    a0.x += b0.x; a0.y += b0.y; a0.z += b0.z; a0.w += b0.w;
    a1.x += b1.x; a1.y += b1.y; a1.z += b1.z; a1.w += b1.w;
    size_t ob = (size_t)wid * CC;
    st_split4(oh + ob + lane * 4, ol + ob + lane * 4, a0);
    st_split4(oh + ob + 128 + lane * 4, ol + ob + 128 + lane * 4, a1);
}

// ---------------- fused weight prep: all 12 matrices in one launch ----------------
__global__ void k_wprep_all(const float* __restrict__ W1s, const float* __restrict__ W2s,
                            const float* __restrict__ W3s, const float* __restrict__ cW1,
                            const float* __restrict__ cW2, const float* __restrict__ cW3,
                            __nv_bfloat16* __restrict__ th, __nv_bfloat16* __restrict__ tl) {
    int i = blockIdx.x * blockDim.x + threadIdx.x;
    if (i >= WTOT) return;
    const float* src;
    size_t dsto;
    int K, N, r;
    if (i < 589824) {
        int m = i / 65536;
        r = i - m * 65536;
        int l = m / 3, j = m - l * 3;
        src = (j == 0 ? W1s : j == 1 ? W2s : W3s) + (size_t)l * 65536;
        dsto = (size_t)m * 65536;
        K = 256; N = 256;
    } else if (i < 655360) {
        r = i - 589824; src = cW1; dsto = WOFF_CW1; K = 256; N = 256;
    } else if (i < 671744) {
        r = i - 655360; src = cW2; dsto = WOFF_CW2; K = 256; N = 64;
    } else {
        r = i - 671744; src = cW3; dsto = WOFF_CW3; K = 64; N = 256;
    }
    int k = r / N, n = r - k * N;
    float v = src[r];
    __nv_bfloat16 h = __float2bfloat16(v);
    size_t d = dsto + (size_t)n * K + k;
    th[d] = h;
    tl[d] = __float2bfloat16(v - __bfloat162float(h));
}

// ---------------- mma.sync GEMM: ldmatrix fragments, cp.async double buffer ----------
// CTA 128x128, BK=32, 8 warps as 4x2, warp tile 32x64.
// MMA issue order interleaves 4 independent accumulators between same-acc reuse.
__global__ void __launch_bounds__(256, 2) k_gemm_mma(
    const __nv_bfloat16* __restrict__ Ah, const __nv_bfloat16* __restrict__ Al,
    const __nv_bfloat16* __restrict__ Wh, const __nv_bfloat16* __restrict__ Wl,
    const float* __restrict__ bias,
    float* __restrict__ outF, __nv_bfloat16* __restrict__ outH,
    __nv_bfloat16* __restrict__ outL,
    int M, int K, int N, int relu) {
    extern __shared__ char smem[];
    uint32_t sbase = s2u(smem);
    int tid = threadIdx.x, lane = tid & 31, warp = tid >> 5;
    int g = lane >> 2, tig = lane & 3;
    int wm = warp >> 1, wn = warp & 1;
    int m0 = blockIdx.x * 128, n0 = blockIdx.y * 128;
    const int NS = K >> 5;

    uint32_t aOff = (uint32_t)(((wm * 32 + (lane & 7) + ((lane >> 3) & 1) * 8) * PK
                               + ((lane >> 4) & 1) * 8) * 2);
    uint32_t bOff = (uint32_t)(((wn * 64 + (lane & 7) + ((lane >> 4) & 1) * 8) * PK
                               + ((lane >> 3) & 1) * 8) * 2);

    float c[2][8][4];
#pragma unroll
    for (int m = 0; m < 2; m++)
#pragma unroll
        for (int n = 0; n < 8; n++)
#pragma unroll
            for (int i = 0; i < 4; i++) c[m][n][i] = 0.f;

    auto issue = [&](int s) {
        uint32_t base = sbase + (uint32_t)(s & 1) * STAGE_B;
        int kb = s * 32;
#pragma unroll
        for (int it = 0; it < 8; it++) {
            int ch = tid + it * 256;
            int sel = ch >> 9;                 // 0=Ah 1=Al 2=Bh 3=Bl
            int idx = ch & 511;
            int row = idx >> 2, i = idx & 3;
            uint32_t dstp = base + (uint32_t)sel * MAT_B + (uint32_t)row * 80u + (uint32_t)i * 16u;
            const __nv_bfloat16* gp;
            uint32_t sz = 16;
            if (sel < 2) {
                int gr = m0 + row;
                gp = (sel == 0 ? Ah : Al);
                if (gr < M) gp += (size_t)gr * K + kb + i * 8; else sz = 0;
            } else {
                int gc = n0 + row;
                gp = (sel == 2 ? Wh : Wl);
                if (gc < N) gp += (size_t)gc * K + kb + i * 8; else sz = 0;
            }
            cp16(dstp, gp, sz);
        }
    };

    issue(0);
    CP_COMMIT();
    for (int s = 0; s < NS; s++) {
        if (s + 1 < NS) { issue(s + 1); CP_COMMIT(); CP_WAIT1(); }
        else            { CP_WAIT0(); }
        __syncthreads();

        uint32_t stg = sbase + (uint32_t)(s & 1) * STAGE_B;
        uint32_t aHb = stg + aOff;
        uint32_t aLb = stg + MAT_B + aOff;
        uint32_t bHb = stg + 2u * MAT_B + bOff;
        uint32_t bLb = stg + 3u * MAT_B + bOff;

#pragma unroll
        for (int ks = 0; ks < 2; ks++) {
            uint32_t ko = (uint32_t)(ks * 16 * 2);
            unsigned aH[2][4], aL[2][4];
#pragma unroll
            for (int m = 0; m < 2; m++) {
                uint32_t mo = (uint32_t)(m * 16 * PK * 2) + ko;
                LDSM4(aH[m], aHb + mo);
                LDSM4(aL[m], aLb + mo);
            }
#pragma unroll
            for (int p = 0; p < 4; p++) {
                uint32_t po = (uint32_t)(p * 16 * PK * 2) + ko;
                unsigned bH[4], bL[4];
                LDSM4(bH, bHb + po);
                LDSM4(bL, bLb + po);
                // 4 independent accumulators between same-acc reuses;
                // per-acc product order stays HH, HL, LH (bit-identical math)
                MMA(c[0][2 * p],     aH[0], bH[0], bH[1]);
                MMA(c[1][2 * p],     aH[1], bH[0], bH[1]);
                MMA(c[0][2 * p + 1], aH[0], bH[2], bH[3]);
                MMA(c[1][2 * p + 1], aH[1], bH[2], bH[3]);
                MMA(c[0][2 * p],     aH[0], bL[0], bL[1]);
                MMA(c[1][2 * p],     aH[1], bL[0], bL[1]);
                MMA(c[0][2 * p + 1], aH[0], bL[2], bL[3]);
                MMA(c[1][2 * p + 1], aH[1], bL[2], bL[3]);
                MMA(c[0][2 * p],     aL[0], bH[0], bH[1]);
                MMA(c[1][2 * p],     aL[1], bH[0], bH[1]);
                MMA(c[0][2 * p + 1], aL[0], bH[2], bH[3]);
                MMA(c[1][2 * p + 1], aL[1], bH[2], bH[3]);
            }
        }
        __syncthreads();
    }

    // epilogue: bias + relu, write fp32 or split hi/lo
#pragma unroll
    for (int m = 0; m < 2; m++) {
        int row = m0 + wm * 32 + m * 16 + g;
#pragma unroll
        for (int n = 0; n < 8; n++) {
            int col = n0 + wn * 64 + n * 8 + 2 * tig;
            if (col >= N) continue;
            float b0 = bias[col], b1 = bias[col + 1];
            float v0 = c[m][n][0] + b0, v1 = c[m][n][1] + b1;
            float v2 = c[m][n][2] + b0, v3 = c[m][n][3] + b1;
            if (relu) {
                v0 = fmaxf(v0, 0.f); v1 = fmaxf(v1, 0.f);
                v2 = fmaxf(v2, 0.f); v3 = fmaxf(v3, 0.f);
            }
            if (outF) {
                if (row < M) *(float2*)(outF + (size_t)row * N + col) = make_float2(v0, v1);
                if (row + 8 < M) *(float2*)(outF + (size_t)(row + 8) * N + col) = make_float2(v2, v3);
            } else {
                __nv_bfloat16 h0 = __float2bfloat16(v0), h1 = __float2bfloat16(v1);
                __nv_bfloat16 h2 = __float2bfloat16(v2), h3 = __float2bfloat16(v3);
                __nv_bfloat16 l0 = __float2bfloat16(v0 - __bfloat162float(h0));
                __nv_bfloat16 l1 = __float2bfloat16(v1 - __bfloat162float(h1));
                __nv_bfloat16 l2 = __float2bfloat16(v2 - __bfloat162float(h2));
                __nv_bfloat16 l3 = __float2bfloat16(v3 - __bfloat162float(h3));
                if (row < M) {
                    *(__nv_bfloat162*)(outH + (size_t)row * N + col) = __halves2bfloat162(h0, h1);
                    *(__nv_bfloat162*)(outL + (size_t)row * N + col) = __halves2bfloat162(l0, l1);
                }
                if (row + 8 < M) {
                    *(__nv_bfloat162*)(outH + (size_t)(row + 8) * N + col) = __halves2bfloat162(h2, h3);
                    *(__nv_bfloat162*)(outL + (size_t)(row + 8) * N + col) = __halves2bfloat162(l2, l3);
                }
            }
        }
    }
}

// ---------------- launch ----------------
extern "C" void kernel_launch(void* const* d_in, const int* in_sizes, int n_in,
                              void* d_out, int out_size) {
    const float* x   = (const float*)d_in[0];
    const int*   src = (const int*)d_in[1];
    const int*   dst = (const int*)d_in[2];
    const float* W1s = (const float*)d_in[3];
    const float* b1s = (const float*)d_in[4];
    const float* W2s = (const float*)d_in[5];
    const float* b2s = (const float*)d_in[6];
    const float* W3s = (const float*)d_in[7];
    const float* b3s = (const float*)d_in[8];
    const float* cW1 = (const float*)d_in[9];
    const float* cb1 = (const float*)d_in[10];
    const float* cW2 = (const float*)d_in[11];
    const float* cb2 = (const float*)d_in[12];
    const float* cW3 = (const float*)d_in[13];
    const float* cb3 = (const float*)d_in[14];
    float* out = (float*)d_out;

    float* s0;
    __nv_bfloat16 *pAh, *pAl, *pBh, *pBl, *wh, *wl;
    int *deg, *off, *pos, *csr, *bsum;
    cudaGetSymbolAddress((void**)&s0, g_s0);
    cudaGetSymbolAddress((void**)&pAh, g_pAh);
    cudaGetSymbolAddress((void**)&pAl, g_pAl);
    cudaGetSymbolAddress((void**)&pBh, g_pBh);
    cudaGetSymbolAddress((void**)&pBl, g_pBl);
    cudaGetSymbolAddress((void**)&wh, g_wh);
    cudaGetSymbolAddress((void**)&wl, g_wl);
    cudaGetSymbolAddress((void**)&deg, g_deg);
    cudaGetSymbolAddress((void**)&off, g_off);
    cudaGetSymbolAddress((void**)&pos, g_pos);
    cudaGetSymbolAddress((void**)&csr, g_csr);
    cudaGetSymbolAddress((void**)&bsum, g_bsum);

    const int SMEM = 2 * (int)STAGE_B;  // 81920
    cudaFuncSetAttribute(k_gemm_mma, cudaFuncAttributeMaxDynamicSharedMemorySize, SMEM);

    // weight prep (one fused launch)
    k_wprep_all<<<(WTOT + 255) / 256, 256>>>(W1s, W2s, W3s, cW1, cW2, cW3, wh, wl);

    // CSR build (multi-block scan)
    k_zero<<<(NN + 255) / 256, 256>>>(deg, NN);
    k_count<<<(EE + 255) / 256, 256>>>(dst, deg);
    k_scan1<<<NB_SCAN, 1024>>>(deg, off, bsum);
    k_scan2<<<1, 64>>>(bsum, off);
    k_scan3<<<(NN + 255) / 256, 256>>>(off, pos, bsum);
    k_scatter<<<(EE + 255) / 256, 256>>>(src, dst, pos, csr);

    const int GB = (NN + 127) / 128;  // 391
    const int aggBlocks = (NN + 7) / 8;
    dim3 g256(GB, 2), g64(GB, 1);

    k_agg_split<<<aggBlocks, 256>>>(x, off, csr, pAh, pAl);
    for (int l = 0; l < 3; l++) {
        k_gemm_mma<<<g256, 256, SMEM>>>(pAh, pAl, wh + WOFF_INNER(l, 0), wl + WOFF_INNER(l, 0),
                                        b1s + (size_t)l * CC, nullptr, pBh, pBl, NN, 256, 256, 1);
        k_gemm_mma<<<g256, 256, SMEM>>>(pBh, pBl, wh + WOFF_INNER(l, 1), wl + WOFF_INNER(l, 1),
                                        b2s + (size_t)l * CC, nullptr, pAh, pAl, NN, 256, 256, 1);
        k_gemm_mma<<<g256, 256, SMEM>>>(pAh, pAl, wh + WOFF_INNER(l, 2), wl + WOFF_INNER(l, 2),
                                        b3s + (size_t)l * CC, s0, nullptr, nullptr, NN, 256, 256, 0);
        k_agg_split<<<aggBlocks, 256>>>(s0, off, csr, pAh, pAl);
    }
    k_gemm_mma<<<g256, 256, SMEM>>>(pAh, pAl, wh + WOFF_CW1, wl + WOFF_CW1,
                                    cb1, nullptr, pBh, pBl, NN, 256, 256, 1);
    k_gemm_mma<<<g64, 256, SMEM>>>(pBh, pBl, wh + WOFF_CW2, wl + WOFF_CW2,
                                   cb2, nullptr, pAh, pAl, NN, 256, 64, 1);
    k_gemm_mma<<<g256, 256, SMEM>>>(pAh, pAl, wh + WOFF_CW3, wl + WOFF_CW3,
                                    cb3, out, nullptr, nullptr, NN, 64, 256, 0);
}